// round 3
// baseline (speedup 1.0000x reference)
#include <cuda_runtime.h>
#include <math.h>

#define BQ 16384
#define DIN 4000
#define HD 512
#define LD 256
#define EBM1 0.6487212707001282f  // exp(0.5)-1

#define BM 128
#define BN 128
#define BKt 16
#define TM 8
#define TN 8

__device__ float g_h[(size_t)BQ * HD];
__device__ float g_q[(size_t)BQ * LD];
__device__ float g_zeta[(size_t)BQ * LD];
__device__ float g_za[(size_t)BQ * LD];
__device__ float g_zb[(size_t)BQ * LD];
__device__ float g_rowpos[BQ];
__device__ float g_rowneg[BQ];
__device__ float g_part[4096];
__device__ float g_ps[16 * HD];
__device__ float g_pss[16 * HD];
__device__ float g_scale[HD];
__device__ float g_shift[HD];

__device__ __forceinline__ float fsigmoid(float x) { return 1.0f / (1.0f + expf(-x)); }

// MODE 0: C = acc+bias   MODE 1: reparam (q->C, zeta->o1, z->o2, zeta->o3)
// MODE 2: gibbs threshold   MODE 3: recon loss partials -> o3
template <int MODE, bool RAG>
__global__ __launch_bounds__(256)
void gemm_k(const float* __restrict__ A, int lda,
            const float* __restrict__ B, int ldb,
            const float* __restrict__ bias,
            float* __restrict__ C, int ldc,
            int M, int N, int K,
            const float* __restrict__ aux,
            float* __restrict__ o1, float* __restrict__ o2, float* __restrict__ o3)
{
    __shared__ float As[BKt][BM + 4];
    __shared__ float Bs[BKt][BN];
    __shared__ float red[256];

    const int tid = threadIdx.x;
    const int tx = tid & 15;
    const int ty = tid >> 4;
    const int rowBase = blockIdx.y * BM;
    const int colBase = blockIdx.x * BN;

    unsigned long long acc[TM][TN / 2];
#pragma unroll
    for (int i = 0; i < TM; i++)
#pragma unroll
        for (int j = 0; j < TN / 2; j++) acc[i][j] = 0ULL;

    for (int k0 = 0; k0 < K; k0 += BKt) {
#pragma unroll
        for (int t = 0; t < 2; t++) {
            int idx = tid + t * 256;
            int ar = idx >> 2, ac = (idx & 3) << 2;
            float4 a4 = *reinterpret_cast<const float4*>(A + (size_t)(rowBase + ar) * lda + (k0 + ac));
            As[ac + 0][ar] = a4.x; As[ac + 1][ar] = a4.y;
            As[ac + 2][ar] = a4.z; As[ac + 3][ar] = a4.w;
        }
#pragma unroll
        for (int t = 0; t < 2; t++) {
            int idx = tid + t * 256;
            int br = idx >> 5, bc = (idx & 31) << 2;
            float4 b4 = make_float4(0.f, 0.f, 0.f, 0.f);
            if (!RAG || (colBase + bc + 4) <= N)
                b4 = *reinterpret_cast<const float4*>(B + (size_t)(k0 + br) * ldb + (colBase + bc));
            *reinterpret_cast<float4*>(&Bs[br][bc]) = b4;
        }
        __syncthreads();
#pragma unroll
        for (int k = 0; k < BKt; k++) {
            float4 a0 = *reinterpret_cast<const float4*>(&As[k][ty * TM]);
            float4 a1 = *reinterpret_cast<const float4*>(&As[k][ty * TM + 4]);
            const unsigned long long* bp = reinterpret_cast<const unsigned long long*>(&Bs[k][tx * TN]);
            unsigned long long b0 = bp[0], b1 = bp[1], b2 = bp[2], b3 = bp[3];
            float av[TM] = {a0.x, a0.y, a0.z, a0.w, a1.x, a1.y, a1.z, a1.w};
#pragma unroll
            for (int i = 0; i < TM; i++) {
                unsigned long long a2;
                asm("mov.b64 %0, {%1,%1};" : "=l"(a2) : "f"(av[i]));
                asm("fma.rn.f32x2 %0, %1, %2, %0;" : "+l"(acc[i][0]) : "l"(a2), "l"(b0));
                asm("fma.rn.f32x2 %0, %1, %2, %0;" : "+l"(acc[i][1]) : "l"(a2), "l"(b1));
                asm("fma.rn.f32x2 %0, %1, %2, %0;" : "+l"(acc[i][2]) : "l"(a2), "l"(b2));
                asm("fma.rn.f32x2 %0, %1, %2, %0;" : "+l"(acc[i][3]) : "l"(a2), "l"(b3));
            }
        }
        __syncthreads();
    }

    float lsum = 0.f;
#pragma unroll
    for (int i = 0; i < TM; i++) {
        int row = rowBase + ty * TM + i;
#pragma unroll
        for (int j = 0; j < TN / 2; j++) {
            float v0, v1;
            asm("mov.b64 {%0,%1}, %2;" : "=f"(v0), "=f"(v1) : "l"(acc[i][j]));
            int c0 = colBase + tx * TN + 2 * j;
#pragma unroll
            for (int e = 0; e < 2; e++) {
                int col = c0 + e;
                float v = e ? v1 : v0;
                if (MODE == 0) {
                    C[(size_t)row * ldc + col] = v + bias[col];
                } else if (MODE == 1) {
                    float q = fsigmoid(v + bias[col]);
                    size_t ix = (size_t)row * N + col;
                    C[ix] = q;
                    float r = aux[ix];
                    float zt = 0.0f;
                    if (r > 1.0f - q)
                        zt = 2.0f * logf(fmaxf(r - (1.0f - q), 0.0f) / q * EBM1 + 1.0f);
                    o1[ix] = zt;
                    o2[ix] = (zt > 0.0f) ? 1.0f : 0.0f;
                    o3[ix] = zt;
                } else if (MODE == 2) {
                    float p = fsigmoid(v + bias[col]);
                    size_t ix = (size_t)row * N + col;
                    C[ix] = (aux[ix] < p) ? 1.0f : 0.0f;
                } else {
                    if (!RAG || col < N) {
                        float d = v + bias[col] - aux[(size_t)row * N + col];
                        lsum += d * d;
                    }
                }
            }
        }
    }
    if (MODE == 3) {
        red[tid] = lsum;
        __syncthreads();
#pragma unroll
        for (int s = 128; s > 0; s >>= 1) {
            if (tid < s) red[tid] += red[tid + s];
            __syncthreads();
        }
        if (tid == 0) o3[blockIdx.y * gridDim.x + blockIdx.x] = red[0];
    }
}

__global__ void bn_stats_part(const float* __restrict__ Hb)
{
    int col = blockIdx.x * 32 + threadIdx.x;
    int r0 = blockIdx.y * (BQ / 16);
    float s = 0.f, ss = 0.f;
    for (int r = threadIdx.y; r < BQ / 16; r += 8) {
        float v = Hb[(size_t)(r0 + r) * HD + col];
        s += v; ss += v * v;
    }
    __shared__ float sh[8][32], sh2[8][32];
    sh[threadIdx.y][threadIdx.x] = s;
    sh2[threadIdx.y][threadIdx.x] = ss;
    __syncthreads();
    if (threadIdx.y == 0) {
        float ts = 0.f, tss = 0.f;
#pragma unroll
        for (int y = 0; y < 8; y++) { ts += sh[y][threadIdx.x]; tss += sh2[y][threadIdx.x]; }
        g_ps[blockIdx.y * HD + col] = ts;
        g_pss[blockIdx.y * HD + col] = tss;
    }
}

__global__ void bn_final(const float* __restrict__ g, const float* __restrict__ be)
{
    int c = blockIdx.x * 256 + threadIdx.x;
    if (c < HD) {
        float s = 0.f, ss = 0.f;
#pragma unroll
        for (int p = 0; p < 16; p++) { s += g_ps[p * HD + c]; ss += g_pss[p * HD + c]; }
        float mu = s / (float)BQ;
        float var = ss / (float)BQ - mu * mu;
        float sc = g[c] * rsqrtf(var + 1e-5f);
        g_scale[c] = sc;
        g_shift[c] = be[c] - mu * sc;
    }
}

__global__ void bn_relu()
{
    size_t i = ((size_t)blockIdx.x * 256 + threadIdx.x) * 4;
    float4 v = *reinterpret_cast<float4*>(&g_h[i]);
    int c = (int)(i & (HD - 1));
    v.x = fmaxf(v.x * g_scale[c + 0] + g_shift[c + 0], 0.f);
    v.y = fmaxf(v.y * g_scale[c + 1] + g_shift[c + 1], 0.f);
    v.z = fmaxf(v.z * g_scale[c + 2] + g_shift[c + 2], 0.f);
    v.w = fmaxf(v.w * g_scale[c + 3] + g_shift[c + 3], 0.f);
    *reinterpret_cast<float4*>(&g_h[i]) = v;
}

// row value = energy(z) [+ sum log_q when useQ] ; energy = z.h + (z@W).z
__global__ __launch_bounds__(256)
void kl_rows(const float* __restrict__ Z, const float* __restrict__ Q,
             const float* __restrict__ h, const float* __restrict__ W,
             float* __restrict__ orow, int useQ)
{
    __shared__ float zsh[16][LD];
    __shared__ float red[256];
    int j = threadIdx.x;
    int r0 = blockIdx.x * 16;
#pragma unroll
    for (int r = 0; r < 16; r++) zsh[r][j] = Z[(size_t)(r0 + r) * LD + j];
    __syncthreads();
    float acc[16];
#pragma unroll
    for (int r = 0; r < 16; r++) acc[r] = 0.f;
    for (int i = 0; i < LD; i++) {
        float w = W[i * LD + j];
#pragma unroll
        for (int r = 0; r < 16; r++) acc[r] += zsh[r][i] * w;
    }
    for (int r = 0; r < 16; r++) {
        float zj = zsh[r][j];
        float val = zj * (h[j] + acc[r]);
        if (useQ) {
            float q = Q[(size_t)(r0 + r) * LD + j];
            q = fminf(fmaxf(q, 1e-7f), 1.0f - 1e-7f);
            val += (zj > 0.5f) ? logf(q) : logf(1.0f - q);
        }
        red[j] = val;
        __syncthreads();
#pragma unroll
        for (int s = 128; s > 0; s >>= 1) {
            if (j < s) red[j] += red[j + s];
            __syncthreads();
        }
        if (j == 0) orow[r0 + r] = red[0];
        __syncthreads();
    }
}

__global__ void finalize_k(float* __restrict__ out)
{
    __shared__ float red[256];
    int t = threadIdx.x;
    float res[3];
    const float* srcs[3];
    int cnts[3] = {4096, BQ, BQ};
    float* d0; float* d1; float* d2;
    d0 = g_part; d1 = g_rowpos; d2 = g_rowneg;
    srcs[0] = d0; srcs[1] = d1; srcs[2] = d2;
#pragma unroll
    for (int p = 0; p < 3; p++) {
        float s = 0.f;
        for (int i = t; i < cnts[p]; i += 256) s += srcs[p][i];
        red[t] = s;
        __syncthreads();
#pragma unroll
        for (int k = 128; k > 0; k >>= 1) {
            if (t < k) red[t] += red[t + k];
            __syncthreads();
        }
        res[p] = red[0];
        __syncthreads();
    }
    if (t == 0) {
        float recon = res[0] / (float)BQ;
        float kl = res[1] / (float)BQ + res[2] / (float)BQ;
        out[0] = -recon - 0.001f * kl;
        out[1] = recon;
        out[2] = kl;
    }
}

extern "C" void kernel_launch(void* const* d_in, const int* in_sizes, int n_in,
                              void* d_out, int out_size)
{
    const float* x      = (const float*)d_in[0];
    const float* rho    = (const float*)d_in[1];
    const float* z_init = (const float*)d_in[2];
    const float* grnd   = (const float*)d_in[3];
    const float* eW1    = (const float*)d_in[4];
    const float* eb1    = (const float*)d_in[5];
    const float* eg1    = (const float*)d_in[6];
    const float* ebe1   = (const float*)d_in[7];
    const float* eW2    = (const float*)d_in[8];
    const float* eb2    = (const float*)d_in[9];
    const float* dW1    = (const float*)d_in[10];
    const float* db1    = (const float*)d_in[11];
    const float* dg1    = (const float*)d_in[12];
    const float* dbe1   = (const float*)d_in[13];
    const float* dW2    = (const float*)d_in[14];
    const float* db2    = (const float*)d_in[15];
    const float* rbm_h  = (const float*)d_in[16];
    const float* rbm_W  = (const float*)d_in[17];

    float* out = (float*)d_out;
    float* out_z = out + 3;
    float* out_zeta = out + 3 + (size_t)BQ * LD;

    float *p_h, *p_q, *p_zeta, *p_za, *p_zb, *p_rp, *p_rn, *p_part;
    cudaGetSymbolAddress((void**)&p_h, g_h);
    cudaGetSymbolAddress((void**)&p_q, g_q);
    cudaGetSymbolAddress((void**)&p_zeta, g_zeta);
    cudaGetSymbolAddress((void**)&p_za, g_za);
    cudaGetSymbolAddress((void**)&p_zb, g_zb);
    cudaGetSymbolAddress((void**)&p_rp, g_rowpos);
    cudaGetSymbolAddress((void**)&p_rn, g_rowneg);
    cudaGetSymbolAddress((void**)&p_part, g_part);

    // encoder layer 1
    gemm_k<0, false><<<dim3(4, 128), 256>>>(x, DIN, eW1, HD, eb1, p_h, HD,
                                            BQ, HD, DIN, nullptr, nullptr, nullptr, nullptr);
    bn_stats_part<<<dim3(16, 16), dim3(32, 8)>>>(p_h);
    bn_final<<<2, 256>>>(eg1, ebe1);
    bn_relu<<<8192, 256>>>();
    // encoder layer 2 + reparam
    gemm_k<1, false><<<dim3(2, 128), 256>>>(p_h, HD, eW2, LD, eb2, p_q, LD,
                                            BQ, LD, HD, rho, p_zeta, out_z, out_zeta);
    // decoder layer 1
    gemm_k<0, false><<<dim3(4, 128), 256>>>(p_zeta, LD, dW1, HD, db1, p_h, HD,
                                            BQ, HD, LD, nullptr, nullptr, nullptr, nullptr);
    bn_stats_part<<<dim3(16, 16), dim3(32, 8)>>>(p_h);
    bn_final<<<2, 256>>>(dg1, dbe1);
    bn_relu<<<8192, 256>>>();
    // decoder layer 2 + fused recon loss
    gemm_k<3, true><<<dim3(32, 128), 256>>>(p_h, HD, dW2, DIN, db2, nullptr, 0,
                                            BQ, DIN, HD, x, nullptr, nullptr, p_part);
    // Gibbs chain: 30 sequential steps
    for (int t = 0; t < 30; t++) {
        const float* zin = (t == 0) ? z_init : ((t & 1) ? p_za : p_zb);
        float* zout = (t & 1) ? p_zb : p_za;
        gemm_k<2, false><<<dim3(2, 128), 256>>>(zin, LD, rbm_W, LD, rbm_h, zout, LD,
                                                BQ, LD, LD, grnd + (size_t)t * BQ * LD,
                                                nullptr, nullptr, nullptr);
    }
    // kl terms: pos (with entropy), neg (z after 30 steps -> g_zb)
    kl_rows<<<1024, 256>>>(out_z, p_q, rbm_h, rbm_W, p_rp, 1);
    kl_rows<<<1024, 256>>>(p_zb, nullptr, rbm_h, rbm_W, p_rn, 0);
    finalize_k<<<1, 256>>>(out);
}

// round 4
// speedup vs baseline: 1.7499x; 1.7499x over previous
#include <cuda_runtime.h>
#include <cuda_bf16.h>
#include <math.h>

#define BQ 16384
#define DIN 4000
#define HD 512
#define LD 256
#define EBM1 0.6487212707001282f  // exp(0.5)-1

#define BM 128
#define BN 128
#define BKt 16
#define TM 8
#define TN 8

__device__ float g_h[(size_t)BQ * HD];
__device__ __nv_bfloat16 g_hb[(size_t)BQ * HD];
__device__ __nv_bfloat16 g_w2b[(size_t)HD * DIN];
__device__ float g_q[(size_t)BQ * LD];
__device__ float g_zeta[(size_t)BQ * LD];
__device__ float g_zb[(size_t)BQ * LD];
__device__ float g_rowpos[BQ];
__device__ float g_rowneg[BQ];
__device__ float g_part[4096];
__device__ float g_ps[16 * HD];
__device__ float g_pss[16 * HD];
__device__ float g_scale[HD];
__device__ float g_shift[HD];

__device__ __forceinline__ float fsigmoid(float x) { return 1.0f / (1.0f + expf(-x)); }
__device__ __forceinline__ unsigned su32(const void* p) { return (unsigned)__cvta_generic_to_shared(p); }

#define LDSM4(a0,a1,a2,a3,addr) \
    asm volatile("ldmatrix.sync.aligned.m8n8.x4.shared.b16 {%0,%1,%2,%3},[%4];" \
                 : "=r"(a0),"=r"(a1),"=r"(a2),"=r"(a3) : "r"(addr))
#define LDSM4T(a0,a1,a2,a3,addr) \
    asm volatile("ldmatrix.sync.aligned.m8n8.x4.trans.shared.b16 {%0,%1,%2,%3},[%4];" \
                 : "=r"(a0),"=r"(a1),"=r"(a2),"=r"(a3) : "r"(addr))
#define MMA16816(c,a0,a1,a2,a3,b0,b1) \
    asm volatile("mma.sync.aligned.m16n8k16.row.col.f32.bf16.bf16.f32 " \
                 "{%0,%1,%2,%3},{%4,%5,%6,%7},{%8,%9},{%0,%1,%2,%3};" \
                 : "+f"((c)[0]),"+f"((c)[1]),"+f"((c)[2]),"+f"((c)[3]) \
                 : "r"(a0),"r"(a1),"r"(a2),"r"(a3),"r"(b0),"r"(b1))
#define CPA16(s,g)      asm volatile("cp.async.cg.shared.global [%0],[%1],16;" :: "r"(s),"l"(g))
#define CPA16Z(s,g,sz)  asm volatile("cp.async.cg.shared.global [%0],[%1],16,%2;" :: "r"(s),"l"(g),"r"(sz))
#define CPCOMMIT()      asm volatile("cp.async.commit_group;")
#define CPWAIT0()       asm volatile("cp.async.wait_group 0;")

// ================= fp32 f32x2 GEMM (encoder path + decoder L1) =================
// MODE 0: C=acc+bias  MODE 1: reparam  (unused modes removed)
template <int MODE>
__global__ __launch_bounds__(256)
void gemm_k(const float* __restrict__ A, int lda,
            const float* __restrict__ B, int ldb,
            const float* __restrict__ bias,
            float* __restrict__ C, int ldc,
            int M, int N, int K,
            const float* __restrict__ aux,
            float* __restrict__ o1, float* __restrict__ o2, float* __restrict__ o3)
{
    __shared__ float As[BKt][BM + 4];
    __shared__ float Bs[BKt][BN];

    const int tid = threadIdx.x;
    const int tx = tid & 15;
    const int ty = tid >> 4;
    const int rowBase = blockIdx.y * BM;
    const int colBase = blockIdx.x * BN;

    unsigned long long acc[TM][TN / 2];
#pragma unroll
    for (int i = 0; i < TM; i++)
#pragma unroll
        for (int j = 0; j < TN / 2; j++) acc[i][j] = 0ULL;

    for (int k0 = 0; k0 < K; k0 += BKt) {
#pragma unroll
        for (int t = 0; t < 2; t++) {
            int idx = tid + t * 256;
            int ar = idx >> 2, ac = (idx & 3) << 2;
            float4 a4 = *reinterpret_cast<const float4*>(A + (size_t)(rowBase + ar) * lda + (k0 + ac));
            As[ac + 0][ar] = a4.x; As[ac + 1][ar] = a4.y;
            As[ac + 2][ar] = a4.z; As[ac + 3][ar] = a4.w;
        }
#pragma unroll
        for (int t = 0; t < 2; t++) {
            int idx = tid + t * 256;
            int br = idx >> 5, bc = (idx & 31) << 2;
            float4 b4 = *reinterpret_cast<const float4*>(B + (size_t)(k0 + br) * ldb + (colBase + bc));
            *reinterpret_cast<float4*>(&Bs[br][bc]) = b4;
        }
        __syncthreads();
#pragma unroll
        for (int k = 0; k < BKt; k++) {
            float4 a0 = *reinterpret_cast<const float4*>(&As[k][ty * TM]);
            float4 a1 = *reinterpret_cast<const float4*>(&As[k][ty * TM + 4]);
            const unsigned long long* bp = reinterpret_cast<const unsigned long long*>(&Bs[k][tx * TN]);
            unsigned long long b0 = bp[0], b1 = bp[1], b2 = bp[2], b3 = bp[3];
            float av[TM] = {a0.x, a0.y, a0.z, a0.w, a1.x, a1.y, a1.z, a1.w};
#pragma unroll
            for (int i = 0; i < TM; i++) {
                unsigned long long a2;
                asm("mov.b64 %0, {%1,%1};" : "=l"(a2) : "f"(av[i]));
                asm("fma.rn.f32x2 %0, %1, %2, %0;" : "+l"(acc[i][0]) : "l"(a2), "l"(b0));
                asm("fma.rn.f32x2 %0, %1, %2, %0;" : "+l"(acc[i][1]) : "l"(a2), "l"(b1));
                asm("fma.rn.f32x2 %0, %1, %2, %0;" : "+l"(acc[i][2]) : "l"(a2), "l"(b2));
                asm("fma.rn.f32x2 %0, %1, %2, %0;" : "+l"(acc[i][3]) : "l"(a2), "l"(b3));
            }
        }
        __syncthreads();
    }

#pragma unroll
    for (int i = 0; i < TM; i++) {
        int row = rowBase + ty * TM + i;
#pragma unroll
        for (int j = 0; j < TN / 2; j++) {
            float v0, v1;
            asm("mov.b64 {%0,%1}, %2;" : "=f"(v0), "=f"(v1) : "l"(acc[i][j]));
            int c0 = colBase + tx * TN + 2 * j;
#pragma unroll
            for (int e = 0; e < 2; e++) {
                int col = c0 + e;
                float v = e ? v1 : v0;
                if (MODE == 0) {
                    C[(size_t)row * ldc + col] = v + bias[col];
                } else {
                    float q = fsigmoid(v + bias[col]);
                    size_t ix = (size_t)row * N + col;
                    C[ix] = q;
                    float r = aux[ix];
                    float zt = 0.0f;
                    if (r > 1.0f - q)
                        zt = 2.0f * logf(fmaxf(r - (1.0f - q), 0.0f) / q * EBM1 + 1.0f);
                    o1[ix] = zt;
                    o2[ix] = (zt > 0.0f) ? 1.0f : 0.0f;
                    o3[ix] = zt;
                }
            }
        }
    }
}

// ================= bf16 MMA GEMM4 + fused recon-loss =================
// C = hd_bf16 @ W2_bf16 + bias ; partial sum of (C - x)^2 per block
#define G4_APITCH 40
#define G4_BPITCH 136
__global__ __launch_bounds__(256)
void gemm4_loss(const __nv_bfloat16* __restrict__ Ahb,
                const __nv_bfloat16* __restrict__ Bw,
                const float* __restrict__ bias,
                const float* __restrict__ X,
                float* __restrict__ part)
{
    __shared__ __nv_bfloat16 Ash[2][128 * G4_APITCH];
    __shared__ __nv_bfloat16 Bsh[2][32 * G4_BPITCH];
    __shared__ float red[256];

    const int tid = threadIdx.x;
    const int lane = tid & 31;
    const int w = tid >> 5;
    const int wm = w & 3;            // warp row (4 along M)
    const int wnn = (w >> 2) * 64;   // warp col (2 along N)
    const int m0 = blockIdx.y * 128;
    const int n0 = blockIdx.x * 128;

    // cp.async assignments
    const int av_r0 = tid >> 2, av_c0 = (tid & 3) * 8;             // A vec 1
    const int av_r1 = (tid + 256) >> 2, av_c1 = ((tid + 256) & 3) * 8;
    const int bv_r0 = tid >> 4, bv_c0 = (tid & 15) * 8;
    const int bv_r1 = (tid + 256) >> 4, bv_c1 = ((tid + 256) & 15) * 8;

    auto load_stage = [&](int buf, int k0) {
        unsigned sa = su32(&Ash[buf][0]);
        CPA16(sa + (av_r0 * G4_APITCH + av_c0) * 2,
              Ahb + (size_t)(m0 + av_r0) * HD + k0 + av_c0);
        CPA16(sa + (av_r1 * G4_APITCH + av_c1) * 2,
              Ahb + (size_t)(m0 + av_r1) * HD + k0 + av_c1);
        unsigned sb = su32(&Bsh[buf][0]);
        {
            int gc = n0 + bv_c0;
            unsigned sz = (gc < DIN) ? 16u : 0u;
            const __nv_bfloat16* src = Bw + (size_t)(k0 + bv_r0) * DIN + (sz ? gc : 0);
            CPA16Z(sb + (bv_r0 * G4_BPITCH + bv_c0) * 2, src, sz);
        }
        {
            int gc = n0 + bv_c1;
            unsigned sz = (gc < DIN) ? 16u : 0u;
            const __nv_bfloat16* src = Bw + (size_t)(k0 + bv_r1) * DIN + (sz ? gc : 0);
            CPA16Z(sb + (bv_r1 * G4_BPITCH + bv_c1) * 2, src, sz);
        }
        CPCOMMIT();
    };

    float c[2][8][4];
#pragma unroll
    for (int i = 0; i < 2; i++)
#pragma unroll
        for (int j = 0; j < 8; j++)
#pragma unroll
            for (int e = 0; e < 4; e++) c[i][j][e] = 0.f;

    const int rA8 = (lane & 7) + 8 * ((lane >> 3) & 1);
    const int cA8 = 8 * (lane >> 4);
    const int rB8 = (lane & 7) + 8 * ((lane >> 3) & 1);
    const int cB8 = 8 * (lane >> 4);

    load_stage(0, 0);
    for (int ks = 0; ks < 16; ks++) {
        CPWAIT0();
        __syncthreads();
        if (ks + 1 < 16) load_stage((ks + 1) & 1, (ks + 1) * 32);
        int buf = ks & 1;
        unsigned abase = su32(&Ash[buf][0]);
        unsigned bbase = su32(&Bsh[buf][0]);
#pragma unroll
        for (int kt = 0; kt < 2; kt++) {
            unsigned a[2][4];
#pragma unroll
            for (int mt = 0; mt < 2; mt++) {
                unsigned addr = abase + ((wm * 32 + mt * 16 + rA8) * G4_APITCH + kt * 16 + cA8) * 2;
                LDSM4(a[mt][0], a[mt][1], a[mt][2], a[mt][3], addr);
            }
#pragma unroll
            for (int ntp = 0; ntp < 4; ntp++) {
                unsigned b0, b1, b2, b3;
                unsigned addr = bbase + ((kt * 16 + rB8) * G4_BPITCH + wnn + ntp * 16 + cB8) * 2;
                LDSM4T(b0, b1, b2, b3, addr);
#pragma unroll
                for (int mt = 0; mt < 2; mt++) {
                    MMA16816(c[mt][2 * ntp], a[mt][0], a[mt][1], a[mt][2], a[mt][3], b0, b1);
                    MMA16816(c[mt][2 * ntp + 1], a[mt][0], a[mt][1], a[mt][2], a[mt][3], b2, b3);
                }
            }
        }
        __syncthreads();
    }

    // epilogue: d^2 accumulation
    float lsum = 0.f;
    const int gid = lane >> 2;
    const int cpair = (lane & 3) << 1;
#pragma unroll
    for (int mt = 0; mt < 2; mt++) {
#pragma unroll
        for (int nt = 0; nt < 8; nt++) {
            int col = n0 + wnn + nt * 8 + cpair;
            if (col < DIN) {
                float b0v = bias[col], b1v = bias[col + 1];
#pragma unroll
                for (int half = 0; half < 2; half++) {
                    int row = m0 + wm * 32 + mt * 16 + gid + half * 8;
                    float2 xx = *reinterpret_cast<const float2*>(X + (size_t)row * DIN + col);
                    float d0 = c[mt][nt][half * 2] + b0v - xx.x;
                    float d1 = c[mt][nt][half * 2 + 1] + b1v - xx.y;
                    lsum += d0 * d0 + d1 * d1;
                }
            }
        }
    }
    red[tid] = lsum;
    __syncthreads();
#pragma unroll
    for (int s = 128; s > 0; s >>= 1) {
        if (tid < s) red[tid] += red[tid + s];
        __syncthreads();
    }
    if (tid == 0) part[blockIdx.y * gridDim.x + blockIdx.x] = red[0];
}

// ================= fused 30-step Gibbs (W + z in smem, bf16 MMA) =================
#define GR 64
#define WP 264
#define ZP 264
__global__ __launch_bounds__(256)
void gibbs_fused(const float* __restrict__ z_init, const float* __restrict__ grnd,
                 const float* __restrict__ rbm_h, const float* __restrict__ rbm_W,
                 float* __restrict__ zout)
{
    extern __shared__ __align__(16) unsigned char smraw[];
    __nv_bfloat16* Wsh = reinterpret_cast<__nv_bfloat16*>(smraw);   // 256*WP
    __nv_bfloat16* Z0 = Wsh + 256 * WP;                              // GR*ZP
    __nv_bfloat16* Z1 = Z0 + GR * ZP;
    float* hsh = reinterpret_cast<float*>(Z1 + GR * ZP);

    const int tid = threadIdx.x;
    const int lane = tid & 31;
    const int w = tid >> 5;
    const int wm = w & 3;              // 4 warps along rows (16 each)
    const int wn = (w >> 2) << 7;      // 2 warps along cols (128 each)
    const int rowBase = blockIdx.x * GR;

    for (int i = tid; i < 256 * 256; i += 256) {
        int r = i >> 8, cc = i & 255;
        Wsh[r * WP + cc] = __float2bfloat16_rn(rbm_W[i]);
    }
    if (tid < 256) hsh[tid] = rbm_h[tid];
    for (int i = tid; i < GR * 256; i += 256) {
        int r = i >> 8, cc = i & 255;
        Z0[r * ZP + cc] = __float2bfloat16_rn(z_init[(size_t)(rowBase + r) * LD + cc]);
    }
    __syncthreads();

    const int rA8 = (lane & 7) + 8 * ((lane >> 3) & 1);
    const int cA8 = 8 * (lane >> 4);
    const int rB8 = (lane & 7) + 8 * ((lane >> 3) & 1);
    const int cB8 = 8 * (lane >> 4);
    const int gid = lane >> 2;
    const int cpair = (lane & 3) << 1;

    __nv_bfloat16* zcur = Z0;
    __nv_bfloat16* znxt = Z1;

    for (int t = 0; t < 30; t++) {
        float c[16][4];
#pragma unroll
        for (int j = 0; j < 16; j++)
#pragma unroll
            for (int e = 0; e < 4; e++) c[j][e] = 0.f;

        unsigned abase = su32(zcur) + (((wm << 4) + rA8) * ZP + cA8) * 2;
        unsigned bbase = su32(Wsh);
#pragma unroll 4
        for (int k0 = 0; k0 < 256; k0 += 16) {
            unsigned a0, a1, a2, a3;
            LDSM4(a0, a1, a2, a3, abase + k0 * 2);
#pragma unroll
            for (int ntp = 0; ntp < 8; ntp++) {
                unsigned b0, b1, b2, b3;
                unsigned addr = bbase + ((k0 + rB8) * WP + wn + ntp * 16 + cB8) * 2;
                LDSM4T(b0, b1, b2, b3, addr);
                MMA16816(c[2 * ntp], a0, a1, a2, a3, b0, b1);
                MMA16816(c[2 * ntp + 1], a0, a1, a2, a3, b2, b3);
            }
        }

        // epilogue: p = sigmoid(h + logits); z' = (r < p)
#pragma unroll
        for (int nt = 0; nt < 16; nt++) {
            int col = wn + nt * 8 + cpair;
            float h0 = hsh[col], h1 = hsh[col + 1];
#pragma unroll
            for (int half = 0; half < 2; half++) {
                int rloc = (wm << 4) + gid + half * 8;
                size_t gro = ((size_t)t * BQ + rowBase + rloc) * LD + col;
                float2 rr = *reinterpret_cast<const float2*>(grnd + gro);
                float p0 = fsigmoid(h0 + c[nt][half * 2]);
                float p1 = fsigmoid(h1 + c[nt][half * 2 + 1]);
                float z0f = (rr.x < p0) ? 1.f : 0.f;
                float z1f = (rr.y < p1) ? 1.f : 0.f;
                if (t == 29) {
                    *reinterpret_cast<float2*>(zout + (size_t)(rowBase + rloc) * LD + col) =
                        make_float2(z0f, z1f);
                } else {
                    __nv_bfloat162 pz;
                    pz.x = __float2bfloat16_rn(z0f);
                    pz.y = __float2bfloat16_rn(z1f);
                    *reinterpret_cast<__nv_bfloat162*>(znxt + rloc * ZP + col) = pz;
                }
            }
        }
        __syncthreads();
        __nv_bfloat16* tmp = zcur; zcur = znxt; znxt = tmp;
    }
}

// ================= BN + misc =================
__global__ void bn_stats_part(const float* __restrict__ Hb)
{
    int col = blockIdx.x * 32 + threadIdx.x;
    int r0 = blockIdx.y * (BQ / 16);
    float s = 0.f, ss = 0.f;
    for (int r = threadIdx.y; r < BQ / 16; r += 8) {
        float v = Hb[(size_t)(r0 + r) * HD + col];
        s += v; ss += v * v;
    }
    __shared__ float sh[8][32], sh2[8][32];
    sh[threadIdx.y][threadIdx.x] = s;
    sh2[threadIdx.y][threadIdx.x] = ss;
    __syncthreads();
    if (threadIdx.y == 0) {
        float ts = 0.f, tss = 0.f;
#pragma unroll
        for (int y = 0; y < 8; y++) { ts += sh[y][threadIdx.x]; tss += sh2[y][threadIdx.x]; }
        g_ps[blockIdx.y * HD + col] = ts;
        g_pss[blockIdx.y * HD + col] = tss;
    }
}

__global__ void bn_final(const float* __restrict__ g, const float* __restrict__ be)
{
    int c = blockIdx.x * 256 + threadIdx.x;
    if (c < HD) {
        float s = 0.f, ss = 0.f;
#pragma unroll
        for (int p = 0; p < 16; p++) { s += g_ps[p * HD + c]; ss += g_pss[p * HD + c]; }
        float mu = s / (float)BQ;
        float var = ss / (float)BQ - mu * mu;
        float sc = g[c] * rsqrtf(var + 1e-5f);
        g_scale[c] = sc;
        g_shift[c] = be[c] - mu * sc;
    }
}

template <int WB>
__global__ void bn_relu()
{
    size_t i = ((size_t)blockIdx.x * 256 + threadIdx.x) * 4;
    float4 v = *reinterpret_cast<float4*>(&g_h[i]);
    int c = (int)(i & (HD - 1));
    v.x = fmaxf(v.x * g_scale[c + 0] + g_shift[c + 0], 0.f);
    v.y = fmaxf(v.y * g_scale[c + 1] + g_shift[c + 1], 0.f);
    v.z = fmaxf(v.z * g_scale[c + 2] + g_shift[c + 2], 0.f);
    v.w = fmaxf(v.w * g_scale[c + 3] + g_shift[c + 3], 0.f);
    if (WB) {
        __nv_bfloat162 p0, p1;
        p0.x = __float2bfloat16_rn(v.x); p0.y = __float2bfloat16_rn(v.y);
        p1.x = __float2bfloat16_rn(v.z); p1.y = __float2bfloat16_rn(v.w);
        *reinterpret_cast<__nv_bfloat162*>(&g_hb[i]) = p0;
        *reinterpret_cast<__nv_bfloat162*>(&g_hb[i + 2]) = p1;
    } else {
        *reinterpret_cast<float4*>(&g_h[i]) = v;
    }
}

__global__ void cvt_w2(const float* __restrict__ w)
{
    int i = blockIdx.x * 256 + threadIdx.x;
    if (i < HD * DIN) g_w2b[i] = __float2bfloat16_rn(w[i]);
}

__global__ __launch_bounds__(256)
void kl_rows(const float* __restrict__ Z, const float* __restrict__ Q,
             const float* __restrict__ h, const float* __restrict__ W,
             float* __restrict__ orow, int useQ)
{
    __shared__ float zsh[16][LD];
    __shared__ float red[256];
    int j = threadIdx.x;
    int r0 = blockIdx.x * 16;
#pragma unroll
    for (int r = 0; r < 16; r++) zsh[r][j] = Z[(size_t)(r0 + r) * LD + j];
    __syncthreads();
    float acc[16];
#pragma unroll
    for (int r = 0; r < 16; r++) acc[r] = 0.f;
    for (int i = 0; i < LD; i++) {
        float wv = W[i * LD + j];
#pragma unroll
        for (int r = 0; r < 16; r++) acc[r] += zsh[r][i] * wv;
    }
    for (int r = 0; r < 16; r++) {
        float zj = zsh[r][j];
        float val = zj * (h[j] + acc[r]);
        if (useQ) {
            float q = Q[(size_t)(r0 + r) * LD + j];
            q = fminf(fmaxf(q, 1e-7f), 1.0f - 1e-7f);
            val += (zj > 0.5f) ? logf(q) : logf(1.0f - q);
        }
        red[j] = val;
        __syncthreads();
#pragma unroll
        for (int s = 128; s > 0; s >>= 1) {
            if (j < s) red[j] += red[j + s];
            __syncthreads();
        }
        if (j == 0) orow[r0 + r] = red[0];
        __syncthreads();
    }
}

__global__ void finalize_k(float* __restrict__ out)
{
    __shared__ float red[256];
    int t = threadIdx.x;
    float res[3];
    const float* srcs[3] = {g_part, g_rowpos, g_rowneg};
    int cnts[3] = {4096, BQ, BQ};
#pragma unroll
    for (int p = 0; p < 3; p++) {
        float s = 0.f;
        for (int i = t; i < cnts[p]; i += 256) s += srcs[p][i];
        red[t] = s;
        __syncthreads();
#pragma unroll
        for (int k = 128; k > 0; k >>= 1) {
            if (t < k) red[t] += red[t + k];
            __syncthreads();
        }
        res[p] = red[0];
        __syncthreads();
    }
    if (t == 0) {
        float recon = res[0] / (float)BQ;
        float kl = res[1] / (float)BQ + res[2] / (float)BQ;
        out[0] = -recon - 0.001f * kl;
        out[1] = recon;
        out[2] = kl;
    }
}

extern "C" void kernel_launch(void* const* d_in, const int* in_sizes, int n_in,
                              void* d_out, int out_size)
{
    const float* x      = (const float*)d_in[0];
    const float* rho    = (const float*)d_in[1];
    const float* z_init = (const float*)d_in[2];
    const float* grnd   = (const float*)d_in[3];
    const float* eW1    = (const float*)d_in[4];
    const float* eb1    = (const float*)d_in[5];
    const float* eg1    = (const float*)d_in[6];
    const float* ebe1   = (const float*)d_in[7];
    const float* eW2    = (const float*)d_in[8];
    const float* eb2    = (const float*)d_in[9];
    const float* dW1    = (const float*)d_in[10];
    const float* db1    = (const float*)d_in[11];
    const float* dg1    = (const float*)d_in[12];
    const float* dbe1   = (const float*)d_in[13];
    const float* dW2    = (const float*)d_in[14];
    const float* db2    = (const float*)d_in[15];
    const float* rbm_h  = (const float*)d_in[16];
    const float* rbm_W  = (const float*)d_in[17];

    float* out = (float*)d_out;
    float* out_z = out + 3;
    float* out_zeta = out + 3 + (size_t)BQ * LD;

    float *p_h, *p_q, *p_zeta, *p_zb, *p_rp, *p_rn, *p_part;
    __nv_bfloat16 *p_hb, *p_w2b;
    cudaGetSymbolAddress((void**)&p_h, g_h);
    cudaGetSymbolAddress((void**)&p_hb, g_hb);
    cudaGetSymbolAddress((void**)&p_w2b, g_w2b);
    cudaGetSymbolAddress((void**)&p_q, g_q);
    cudaGetSymbolAddress((void**)&p_zeta, g_zeta);
    cudaGetSymbolAddress((void**)&p_zb, g_zb);
    cudaGetSymbolAddress((void**)&p_rp, g_rowpos);
    cudaGetSymbolAddress((void**)&p_rn, g_rowneg);
    cudaGetSymbolAddress((void**)&p_part, g_part);

    static int smem_set = 0;
    int gibbs_smem = (256 * WP + 2 * GR * ZP) * 2 + 256 * 4;
    if (!smem_set) {
        cudaFuncSetAttribute(gibbs_fused, cudaFuncAttributeMaxDynamicSharedMemorySize, gibbs_smem);
        smem_set = 1;
    }

    // convert decoder W2 to bf16 (independent; do it first)
    cvt_w2<<<(HD * DIN + 255) / 256, 256>>>(dW2);

    // encoder layer 1 (fp32)
    gemm_k<0><<<dim3(4, 128), 256>>>(x, DIN, eW1, HD, eb1, p_h, HD,
                                     BQ, HD, DIN, nullptr, nullptr, nullptr, nullptr);
    bn_stats_part<<<dim3(16, 16), dim3(32, 8)>>>(p_h);
    bn_final<<<2, 256>>>(eg1, ebe1);
    bn_relu<0><<<8192, 256>>>();
    // encoder layer 2 + reparam (fp32)
    gemm_k<1><<<dim3(2, 128), 256>>>(p_h, HD, eW2, LD, eb2, p_q, LD,
                                     BQ, LD, HD, rho, p_zeta, out_z, out_zeta);
    // decoder layer 1 (fp32)
    gemm_k<0><<<dim3(4, 128), 256>>>(p_zeta, LD, dW1, HD, db1, p_h, HD,
                                     BQ, HD, LD, nullptr, nullptr, nullptr, nullptr);
    bn_stats_part<<<dim3(16, 16), dim3(32, 8)>>>(p_h);
    bn_final<<<2, 256>>>(dg1, dbe1);
    bn_relu<1><<<8192, 256>>>();
    // decoder layer 2 + fused recon loss (bf16 tensor)
    gemm4_loss<<<dim3(32, 128), 256>>>(p_hb, p_w2b, db2, x, p_part);
    // fused 30-step Gibbs (bf16 tensor, W resident in smem)
    gibbs_fused<<<BQ / GR, 256, gibbs_smem>>>(z_init, grnd, rbm_h, rbm_W, p_zb);
    // kl terms
    kl_rows<<<1024, 256>>>(out_z, p_q, rbm_h, rbm_W, p_rp, 1);
    kl_rows<<<1024, 256>>>(p_zb, nullptr, rbm_h, rbm_W, p_rn, 0);
    finalize_k<<<1, 256>>>(out);
}

// round 5
// speedup vs baseline: 1.9232x; 1.0990x over previous
#include <cuda_runtime.h>
#include <cuda_bf16.h>
#include <math.h>

#define BQ 16384
#define DIN 4000
#define HD 512
#define LD 256
#define EBM1 0.6487212707001282f  // exp(0.5)-1

#define BM 128
#define BN 128
#define BKt 16
#define TM 8
#define TN 8

__device__ float g_h[(size_t)BQ * HD];
__device__ __nv_bfloat16 g_hb[(size_t)BQ * HD];
__device__ __nv_bfloat16 g_w2b[(size_t)HD * DIN];
__device__ float g_q[(size_t)BQ * LD];
__device__ float g_zeta[(size_t)BQ * LD];
__device__ float g_zb[(size_t)BQ * LD];
__device__ float g_rowpos[BQ];
__device__ float g_rowneg[BQ];
__device__ float g_part[4096];
__device__ float g_ps[16 * HD];
__device__ float g_pss[16 * HD];
__device__ float g_scale[HD];
__device__ float g_shift[HD];

__device__ __forceinline__ float fsigmoid(float x) { return 1.0f / (1.0f + expf(-x)); }
__device__ __forceinline__ unsigned su32(const void* p) { return (unsigned)__cvta_generic_to_shared(p); }

#define LDSM4(a0,a1,a2,a3,addr) \
    asm volatile("ldmatrix.sync.aligned.m8n8.x4.shared.b16 {%0,%1,%2,%3},[%4];" \
                 : "=r"(a0),"=r"(a1),"=r"(a2),"=r"(a3) : "r"(addr))
#define LDSM4T(a0,a1,a2,a3,addr) \
    asm volatile("ldmatrix.sync.aligned.m8n8.x4.trans.shared.b16 {%0,%1,%2,%3},[%4];" \
                 : "=r"(a0),"=r"(a1),"=r"(a2),"=r"(a3) : "r"(addr))
#define MMA16816(c,a0,a1,a2,a3,b0,b1) \
    asm volatile("mma.sync.aligned.m16n8k16.row.col.f32.bf16.bf16.f32 " \
                 "{%0,%1,%2,%3},{%4,%5,%6,%7},{%8,%9},{%0,%1,%2,%3};" \
                 : "+f"((c)[0]),"+f"((c)[1]),"+f"((c)[2]),"+f"((c)[3]) \
                 : "r"(a0),"r"(a1),"r"(a2),"r"(a3),"r"(b0),"r"(b1))
#define MMATF32(c,a0,a1,a2,a3,b0,b1) \
    asm volatile("mma.sync.aligned.m16n8k8.row.col.f32.tf32.tf32.f32 " \
                 "{%0,%1,%2,%3},{%4,%5,%6,%7},{%8,%9},{%0,%1,%2,%3};" \
                 : "+f"((c)[0]),"+f"((c)[1]),"+f"((c)[2]),"+f"((c)[3]) \
                 : "r"(a0),"r"(a1),"r"(a2),"r"(a3),"r"(b0),"r"(b1))
#define CPA16(s,g)      asm volatile("cp.async.cg.shared.global [%0],[%1],16;" :: "r"(s),"l"(g))
#define CPA16Z(s,g,sz)  asm volatile("cp.async.cg.shared.global [%0],[%1],16,%2;" :: "r"(s),"l"(g),"r"(sz))
#define CPCOMMIT()      asm volatile("cp.async.commit_group;")
#define CPWAIT0()       asm volatile("cp.async.wait_group 0;")

__device__ __forceinline__ void tf32_split(float x, unsigned& hi, unsigned& lo) {
    asm("cvt.rna.tf32.f32 %0,%1;" : "=r"(hi) : "f"(x));
    float l = x - __uint_as_float(hi);
    asm("cvt.rna.tf32.f32 %0,%1;" : "=r"(lo) : "f"(l));
}

// ================= tf32x3 split GEMM (fp32-equivalent accuracy, tensor cores) =================
// C = A@B + bias ; A [M,K] row-major, B [K,N] row-major. Grid (N/128, M/128), 256 thr.
__global__ __launch_bounds__(256)
void gemm_tf32(const float* __restrict__ A, int lda,
               const float* __restrict__ B, int ldb,
               const float* __restrict__ bias,
               float* __restrict__ C, int ldc, int K)
{
    __shared__ float As[BKt][BM + 4];
    __shared__ float Bs[BKt][BN + 4];

    const int tid = threadIdx.x;
    const int lane = tid & 31;
    const int w = tid >> 5;
    const int wm = w & 3;        // 4 warps along M (32 rows each)
    const int wn = w >> 2;       // 2 warps along N (64 cols each)
    const int m0 = blockIdx.y * BM;
    const int n0 = blockIdx.x * BN;
    const int r = lane >> 2;
    const int q = lane & 3;

    float c[2][8][4];
#pragma unroll
    for (int i = 0; i < 2; i++)
#pragma unroll
        for (int j = 0; j < 8; j++)
#pragma unroll
            for (int e = 0; e < 4; e++) c[i][j][e] = 0.f;

    for (int k0 = 0; k0 < K; k0 += BKt) {
#pragma unroll
        for (int t = 0; t < 2; t++) {
            int idx = tid + t * 256;
            int ar = idx >> 2, ac = (idx & 3) << 2;
            float4 a4 = *reinterpret_cast<const float4*>(A + (size_t)(m0 + ar) * lda + (k0 + ac));
            As[ac + 0][ar] = a4.x; As[ac + 1][ar] = a4.y;
            As[ac + 2][ar] = a4.z; As[ac + 3][ar] = a4.w;
        }
#pragma unroll
        for (int t = 0; t < 2; t++) {
            int idx = tid + t * 256;
            int br = idx >> 5, bc = (idx & 31) << 2;
            float4 b4 = *reinterpret_cast<const float4*>(B + (size_t)(k0 + br) * ldb + (n0 + bc));
            Bs[br][bc + 0] = b4.x; Bs[br][bc + 1] = b4.y;
            Bs[br][bc + 2] = b4.z; Bs[br][bc + 3] = b4.w;
        }
        __syncthreads();
#pragma unroll
        for (int ks = 0; ks < 2; ks++) {
            const int kb = ks * 8;
            unsigned ahi[2][4], alo[2][4];
#pragma unroll
            for (int mt = 0; mt < 2; mt++) {
                const int mB = wm * 32 + mt * 16;
                float av[4];
                av[0] = As[kb + q][mB + r];
                av[1] = As[kb + q][mB + r + 8];
                av[2] = As[kb + 4 + q][mB + r];
                av[3] = As[kb + 4 + q][mB + r + 8];
#pragma unroll
                for (int i = 0; i < 4; i++) tf32_split(av[i], ahi[mt][i], alo[mt][i]);
            }
#pragma unroll
            for (int nt = 0; nt < 8; nt++) {
                const int nB = wn * 64 + nt * 8;
                float bv0 = Bs[kb + q][nB + r];
                float bv1 = Bs[kb + 4 + q][nB + r];
                unsigned bh0, bl0, bh1, bl1;
                tf32_split(bv0, bh0, bl0);
                tf32_split(bv1, bh1, bl1);
#pragma unroll
                for (int mt = 0; mt < 2; mt++) {
                    MMATF32(c[mt][nt], ahi[mt][0], ahi[mt][1], ahi[mt][2], ahi[mt][3], bh0, bh1);
                    MMATF32(c[mt][nt], ahi[mt][0], ahi[mt][1], ahi[mt][2], ahi[mt][3], bl0, bl1);
                    MMATF32(c[mt][nt], alo[mt][0], alo[mt][1], alo[mt][2], alo[mt][3], bh0, bh1);
                }
            }
        }
        __syncthreads();
    }

#pragma unroll
    for (int mt = 0; mt < 2; mt++) {
#pragma unroll
        for (int nt = 0; nt < 8; nt++) {
            int col = n0 + wn * 64 + nt * 8 + 2 * q;
            float2 bb = *reinterpret_cast<const float2*>(bias + col);
#pragma unroll
            for (int half = 0; half < 2; half++) {
                int row = m0 + wm * 32 + mt * 16 + r + half * 8;
                float2 vv = make_float2(c[mt][nt][half * 2] + bb.x,
                                        c[mt][nt][half * 2 + 1] + bb.y);
                *reinterpret_cast<float2*>(C + (size_t)row * ldc + col) = vv;
            }
        }
    }
}

// ================= fp32 f32x2 GEMM (encoder L2 + reparam only) =================
template <int MODE>
__global__ __launch_bounds__(256)
void gemm_k(const float* __restrict__ A, int lda,
            const float* __restrict__ B, int ldb,
            const float* __restrict__ bias,
            float* __restrict__ C, int ldc,
            int M, int N, int K,
            const float* __restrict__ aux,
            float* __restrict__ o1, float* __restrict__ o2, float* __restrict__ o3)
{
    __shared__ float As[BKt][BM + 4];
    __shared__ float Bs[BKt][BN];

    const int tid = threadIdx.x;
    const int tx = tid & 15;
    const int ty = tid >> 4;
    const int rowBase = blockIdx.y * BM;
    const int colBase = blockIdx.x * BN;

    unsigned long long acc[TM][TN / 2];
#pragma unroll
    for (int i = 0; i < TM; i++)
#pragma unroll
        for (int j = 0; j < TN / 2; j++) acc[i][j] = 0ULL;

    for (int k0 = 0; k0 < K; k0 += BKt) {
#pragma unroll
        for (int t = 0; t < 2; t++) {
            int idx = tid + t * 256;
            int ar = idx >> 2, ac = (idx & 3) << 2;
            float4 a4 = *reinterpret_cast<const float4*>(A + (size_t)(rowBase + ar) * lda + (k0 + ac));
            As[ac + 0][ar] = a4.x; As[ac + 1][ar] = a4.y;
            As[ac + 2][ar] = a4.z; As[ac + 3][ar] = a4.w;
        }
#pragma unroll
        for (int t = 0; t < 2; t++) {
            int idx = tid + t * 256;
            int br = idx >> 5, bc = (idx & 31) << 2;
            float4 b4 = *reinterpret_cast<const float4*>(B + (size_t)(k0 + br) * ldb + (colBase + bc));
            *reinterpret_cast<float4*>(&Bs[br][bc]) = b4;
        }
        __syncthreads();
#pragma unroll
        for (int k = 0; k < BKt; k++) {
            float4 a0 = *reinterpret_cast<const float4*>(&As[k][ty * TM]);
            float4 a1 = *reinterpret_cast<const float4*>(&As[k][ty * TM + 4]);
            const unsigned long long* bp = reinterpret_cast<const unsigned long long*>(&Bs[k][tx * TN]);
            unsigned long long b0 = bp[0], b1 = bp[1], b2 = bp[2], b3 = bp[3];
            float av[TM] = {a0.x, a0.y, a0.z, a0.w, a1.x, a1.y, a1.z, a1.w};
#pragma unroll
            for (int i = 0; i < TM; i++) {
                unsigned long long a2;
                asm("mov.b64 %0, {%1,%1};" : "=l"(a2) : "f"(av[i]));
                asm("fma.rn.f32x2 %0, %1, %2, %0;" : "+l"(acc[i][0]) : "l"(a2), "l"(b0));
                asm("fma.rn.f32x2 %0, %1, %2, %0;" : "+l"(acc[i][1]) : "l"(a2), "l"(b1));
                asm("fma.rn.f32x2 %0, %1, %2, %0;" : "+l"(acc[i][2]) : "l"(a2), "l"(b2));
                asm("fma.rn.f32x2 %0, %1, %2, %0;" : "+l"(acc[i][3]) : "l"(a2), "l"(b3));
            }
        }
        __syncthreads();
    }

#pragma unroll
    for (int i = 0; i < TM; i++) {
        int row = rowBase + ty * TM + i;
#pragma unroll
        for (int j = 0; j < TN / 2; j++) {
            float v0, v1;
            asm("mov.b64 {%0,%1}, %2;" : "=f"(v0), "=f"(v1) : "l"(acc[i][j]));
            int c0 = colBase + tx * TN + 2 * j;
#pragma unroll
            for (int e = 0; e < 2; e++) {
                int col = c0 + e;
                float v = e ? v1 : v0;
                if (MODE == 0) {
                    C[(size_t)row * ldc + col] = v + bias[col];
                } else {
                    float q = fsigmoid(v + bias[col]);
                    size_t ix = (size_t)row * N + col;
                    C[ix] = q;
                    float r = aux[ix];
                    float zt = 0.0f;
                    if (r > 1.0f - q)
                        zt = 2.0f * logf(fmaxf(r - (1.0f - q), 0.0f) / q * EBM1 + 1.0f);
                    o1[ix] = zt;
                    o2[ix] = (zt > 0.0f) ? 1.0f : 0.0f;
                    o3[ix] = zt;
                }
            }
        }
    }
}

// ================= bf16 MMA GEMM4 + fused recon-loss =================
#define G4_APITCH 40
#define G4_BPITCH 136
__global__ __launch_bounds__(256)
void gemm4_loss(const __nv_bfloat16* __restrict__ Ahb,
                const __nv_bfloat16* __restrict__ Bw,
                const float* __restrict__ bias,
                const float* __restrict__ X,
                float* __restrict__ part)
{
    __shared__ __nv_bfloat16 Ash[2][128 * G4_APITCH];
    __shared__ __nv_bfloat16 Bsh[2][32 * G4_BPITCH];
    __shared__ float red[256];

    const int tid = threadIdx.x;
    const int lane = tid & 31;
    const int w = tid >> 5;
    const int wm = w & 3;
    const int wnn = (w >> 2) * 64;
    const int m0 = blockIdx.y * 128;
    const int n0 = blockIdx.x * 128;

    const int av_r0 = tid >> 2, av_c0 = (tid & 3) * 8;
    const int av_r1 = (tid + 256) >> 2, av_c1 = ((tid + 256) & 3) * 8;
    const int bv_r0 = tid >> 4, bv_c0 = (tid & 15) * 8;
    const int bv_r1 = (tid + 256) >> 4, bv_c1 = ((tid + 256) & 15) * 8;

    auto load_stage = [&](int buf, int k0) {
        unsigned sa = su32(&Ash[buf][0]);
        CPA16(sa + (av_r0 * G4_APITCH + av_c0) * 2,
              Ahb + (size_t)(m0 + av_r0) * HD + k0 + av_c0);
        CPA16(sa + (av_r1 * G4_APITCH + av_c1) * 2,
              Ahb + (size_t)(m0 + av_r1) * HD + k0 + av_c1);
        unsigned sb = su32(&Bsh[buf][0]);
        {
            int gc = n0 + bv_c0;
            unsigned sz = (gc < DIN) ? 16u : 0u;
            const __nv_bfloat16* src = Bw + (size_t)(k0 + bv_r0) * DIN + (sz ? gc : 0);
            CPA16Z(sb + (bv_r0 * G4_BPITCH + bv_c0) * 2, src, sz);
        }
        {
            int gc = n0 + bv_c1;
            unsigned sz = (gc < DIN) ? 16u : 0u;
            const __nv_bfloat16* src = Bw + (size_t)(k0 + bv_r1) * DIN + (sz ? gc : 0);
            CPA16Z(sb + (bv_r1 * G4_BPITCH + bv_c1) * 2, src, sz);
        }
        CPCOMMIT();
    };

    float c[2][8][4];
#pragma unroll
    for (int i = 0; i < 2; i++)
#pragma unroll
        for (int j = 0; j < 8; j++)
#pragma unroll
            for (int e = 0; e < 4; e++) c[i][j][e] = 0.f;

    const int rA8 = (lane & 7) + 8 * ((lane >> 3) & 1);
    const int cA8 = 8 * (lane >> 4);
    const int rB8 = (lane & 7) + 8 * ((lane >> 3) & 1);
    const int cB8 = 8 * (lane >> 4);

    load_stage(0, 0);
    for (int ks = 0; ks < 16; ks++) {
        CPWAIT0();
        __syncthreads();
        if (ks + 1 < 16) load_stage((ks + 1) & 1, (ks + 1) * 32);
        int buf = ks & 1;
        unsigned abase = su32(&Ash[buf][0]);
        unsigned bbase = su32(&Bsh[buf][0]);
#pragma unroll
        for (int kt = 0; kt < 2; kt++) {
            unsigned a[2][4];
#pragma unroll
            for (int mt = 0; mt < 2; mt++) {
                unsigned addr = abase + ((wm * 32 + mt * 16 + rA8) * G4_APITCH + kt * 16 + cA8) * 2;
                LDSM4(a[mt][0], a[mt][1], a[mt][2], a[mt][3], addr);
            }
#pragma unroll
            for (int ntp = 0; ntp < 4; ntp++) {
                unsigned b0, b1, b2, b3;
                unsigned addr = bbase + ((kt * 16 + rB8) * G4_BPITCH + wnn + ntp * 16 + cB8) * 2;
                LDSM4T(b0, b1, b2, b3, addr);
#pragma unroll
                for (int mt = 0; mt < 2; mt++) {
                    MMA16816(c[mt][2 * ntp], a[mt][0], a[mt][1], a[mt][2], a[mt][3], b0, b1);
                    MMA16816(c[mt][2 * ntp + 1], a[mt][0], a[mt][1], a[mt][2], a[mt][3], b2, b3);
                }
            }
        }
        __syncthreads();
    }

    float lsum = 0.f;
    const int gid = lane >> 2;
    const int cpair = (lane & 3) << 1;
#pragma unroll
    for (int mt = 0; mt < 2; mt++) {
#pragma unroll
        for (int nt = 0; nt < 8; nt++) {
            int col = n0 + wnn + nt * 8 + cpair;
            if (col < DIN) {
                float b0v = bias[col], b1v = bias[col + 1];
#pragma unroll
                for (int half = 0; half < 2; half++) {
                    int row = m0 + wm * 32 + mt * 16 + gid + half * 8;
                    float2 xx = *reinterpret_cast<const float2*>(X + (size_t)row * DIN + col);
                    float d0 = c[mt][nt][half * 2] + b0v - xx.x;
                    float d1 = c[mt][nt][half * 2 + 1] + b1v - xx.y;
                    lsum += d0 * d0 + d1 * d1;
                }
            }
        }
    }
    red[tid] = lsum;
    __syncthreads();
#pragma unroll
    for (int s = 128; s > 0; s >>= 1) {
        if (tid < s) red[tid] += red[tid + s];
        __syncthreads();
    }
    if (tid == 0) part[blockIdx.y * gridDim.x + blockIdx.x] = red[0];
}

// ================= fused 30-step Gibbs =================
#define GR 64
#define WP 264
#define ZP 264
__global__ __launch_bounds__(256)
void gibbs_fused(const float* __restrict__ z_init, const float* __restrict__ grnd,
                 const float* __restrict__ rbm_h, const float* __restrict__ rbm_W,
                 float* __restrict__ zout)
{
    extern __shared__ __align__(16) unsigned char smraw[];
    __nv_bfloat16* Wsh = reinterpret_cast<__nv_bfloat16*>(smraw);
    __nv_bfloat16* Z0 = Wsh + 256 * WP;
    __nv_bfloat16* Z1 = Z0 + GR * ZP;
    float* hsh = reinterpret_cast<float*>(Z1 + GR * ZP);

    const int tid = threadIdx.x;
    const int lane = tid & 31;
    const int w = tid >> 5;
    const int wm = w & 3;
    const int wn = (w >> 2) << 7;
    const int rowBase = blockIdx.x * GR;

    for (int i = tid; i < 256 * 256; i += 256) {
        int r = i >> 8, cc = i & 255;
        Wsh[r * WP + cc] = __float2bfloat16_rn(rbm_W[i]);
    }
    if (tid < 256) hsh[tid] = rbm_h[tid];
    for (int i = tid; i < GR * 256; i += 256) {
        int r = i >> 8, cc = i & 255;
        Z0[r * ZP + cc] = __float2bfloat16_rn(z_init[(size_t)(rowBase + r) * LD + cc]);
    }
    __syncthreads();

    const int rA8 = (lane & 7) + 8 * ((lane >> 3) & 1);
    const int cA8 = 8 * (lane >> 4);
    const int rB8 = (lane & 7) + 8 * ((lane >> 3) & 1);
    const int cB8 = 8 * (lane >> 4);
    const int gid = lane >> 2;
    const int cpair = (lane & 3) << 1;

    __nv_bfloat16* zcur = Z0;
    __nv_bfloat16* znxt = Z1;

    for (int t = 0; t < 30; t++) {
        float c[16][4];
#pragma unroll
        for (int j = 0; j < 16; j++)
#pragma unroll
            for (int e = 0; e < 4; e++) c[j][e] = 0.f;

        unsigned abase = su32(zcur) + (((wm << 4) + rA8) * ZP + cA8) * 2;
        unsigned bbase = su32(Wsh);
#pragma unroll 4
        for (int k0 = 0; k0 < 256; k0 += 16) {
            unsigned a0, a1, a2, a3;
            LDSM4(a0, a1, a2, a3, abase + k0 * 2);
#pragma unroll
            for (int ntp = 0; ntp < 8; ntp++) {
                unsigned b0, b1, b2, b3;
                unsigned addr = bbase + ((k0 + rB8) * WP + wn + ntp * 16 + cB8) * 2;
                LDSM4T(b0, b1, b2, b3, addr);
                MMA16816(c[2 * ntp], a0, a1, a2, a3, b0, b1);
                MMA16816(c[2 * ntp + 1], a0, a1, a2, a3, b2, b3);
            }
        }

#pragma unroll
        for (int nt = 0; nt < 16; nt++) {
            int col = wn + nt * 8 + cpair;
            float h0 = hsh[col], h1 = hsh[col + 1];
#pragma unroll
            for (int half = 0; half < 2; half++) {
                int rloc = (wm << 4) + gid + half * 8;
                size_t gro = ((size_t)t * BQ + rowBase + rloc) * LD + col;
                float2 rr = *reinterpret_cast<const float2*>(grnd + gro);
                float p0 = fsigmoid(h0 + c[nt][half * 2]);
                float p1 = fsigmoid(h1 + c[nt][half * 2 + 1]);
                float z0f = (rr.x < p0) ? 1.f : 0.f;
                float z1f = (rr.y < p1) ? 1.f : 0.f;
                if (t == 29) {
                    *reinterpret_cast<float2*>(zout + (size_t)(rowBase + rloc) * LD + col) =
                        make_float2(z0f, z1f);
                } else {
                    __nv_bfloat162 pz;
                    pz.x = __float2bfloat16_rn(z0f);
                    pz.y = __float2bfloat16_rn(z1f);
                    *reinterpret_cast<__nv_bfloat162*>(znxt + rloc * ZP + col) = pz;
                }
            }
        }
        __syncthreads();
        __nv_bfloat16* tmp = zcur; zcur = znxt; znxt = tmp;
    }
}

// ================= BN + misc =================
__global__ void bn_stats_part(const float* __restrict__ Hb)
{
    int col = blockIdx.x * 32 + threadIdx.x;
    int r0 = blockIdx.y * (BQ / 16);
    float s = 0.f, ss = 0.f;
    for (int r = threadIdx.y; r < BQ / 16; r += 8) {
        float v = Hb[(size_t)(r0 + r) * HD + col];
        s += v; ss += v * v;
    }
    __shared__ float sh[8][32], sh2[8][32];
    sh[threadIdx.y][threadIdx.x] = s;
    sh2[threadIdx.y][threadIdx.x] = ss;
    __syncthreads();
    if (threadIdx.y == 0) {
        float ts = 0.f, tss = 0.f;
#pragma unroll
        for (int y = 0; y < 8; y++) { ts += sh[y][threadIdx.x]; tss += sh2[y][threadIdx.x]; }
        g_ps[blockIdx.y * HD + col] = ts;
        g_pss[blockIdx.y * HD + col] = tss;
    }
}

__global__ void bn_final(const float* __restrict__ g, const float* __restrict__ be)
{
    int c = blockIdx.x * 256 + threadIdx.x;
    if (c < HD) {
        float s = 0.f, ss = 0.f;
#pragma unroll
        for (int p = 0; p < 16; p++) { s += g_ps[p * HD + c]; ss += g_pss[p * HD + c]; }
        float mu = s / (float)BQ;
        float var = ss / (float)BQ - mu * mu;
        float sc = g[c] * rsqrtf(var + 1e-5f);
        g_scale[c] = sc;
        g_shift[c] = be[c] - mu * sc;
    }
}

template <int WB>
__global__ void bn_relu()
{
    size_t i = ((size_t)blockIdx.x * 256 + threadIdx.x) * 4;
    float4 v = *reinterpret_cast<float4*>(&g_h[i]);
    int c = (int)(i & (HD - 1));
    v.x = fmaxf(v.x * g_scale[c + 0] + g_shift[c + 0], 0.f);
    v.y = fmaxf(v.y * g_scale[c + 1] + g_shift[c + 1], 0.f);
    v.z = fmaxf(v.z * g_scale[c + 2] + g_shift[c + 2], 0.f);
    v.w = fmaxf(v.w * g_scale[c + 3] + g_shift[c + 3], 0.f);
    if (WB) {
        __nv_bfloat162 p0, p1;
        p0.x = __float2bfloat16_rn(v.x); p0.y = __float2bfloat16_rn(v.y);
        p1.x = __float2bfloat16_rn(v.z); p1.y = __float2bfloat16_rn(v.w);
        *reinterpret_cast<__nv_bfloat162*>(&g_hb[i]) = p0;
        *reinterpret_cast<__nv_bfloat162*>(&g_hb[i + 2]) = p1;
    } else {
        *reinterpret_cast<float4*>(&g_h[i]) = v;
    }
}

__global__ void cvt_w2(const float* __restrict__ w)
{
    int i = blockIdx.x * 256 + threadIdx.x;
    if (i < HD * DIN) g_w2b[i] = __float2bfloat16_rn(w[i]);
}

__global__ __launch_bounds__(256)
void kl_rows(const float* __restrict__ Z, const float* __restrict__ Q,
             const float* __restrict__ h, const float* __restrict__ W,
             float* __restrict__ orow, int useQ)
{
    __shared__ float zsh[16][LD];
    __shared__ float red[256];
    int j = threadIdx.x;
    int r0 = blockIdx.x * 16;
#pragma unroll
    for (int r = 0; r < 16; r++) zsh[r][j] = Z[(size_t)(r0 + r) * LD + j];
    __syncthreads();
    float acc[16];
#pragma unroll
    for (int r = 0; r < 16; r++) acc[r] = 0.f;
    for (int i = 0; i < LD; i++) {
        float wv = W[i * LD + j];
#pragma unroll
        for (int r = 0; r < 16; r++) acc[r] += zsh[r][i] * wv;
    }
    for (int r = 0; r < 16; r++) {
        float zj = zsh[r][j];
        float val = zj * (h[j] + acc[r]);
        if (useQ) {
            float q = Q[(size_t)(r0 + r) * LD + j];
            q = fminf(fmaxf(q, 1e-7f), 1.0f - 1e-7f);
            val += (zj > 0.5f) ? logf(q) : logf(1.0f - q);
        }
        red[j] = val;
        __syncthreads();
#pragma unroll
        for (int s = 128; s > 0; s >>= 1) {
            if (j < s) red[j] += red[j + s];
            __syncthreads();
        }
        if (j == 0) orow[r0 + r] = red[0];
        __syncthreads();
    }
}

__global__ void finalize_k(float* __restrict__ out)
{
    __shared__ float red[256];
    int t = threadIdx.x;
    float res[3];
    const float* srcs[3] = {g_part, g_rowpos, g_rowneg};
    int cnts[3] = {4096, BQ, BQ};
#pragma unroll
    for (int p = 0; p < 3; p++) {
        float s = 0.f;
        for (int i = t; i < cnts[p]; i += 256) s += srcs[p][i];
        red[t] = s;
        __syncthreads();
#pragma unroll
        for (int k = 128; k > 0; k >>= 1) {
            if (t < k) red[t] += red[t + k];
            __syncthreads();
        }
        res[p] = red[0];
        __syncthreads();
    }
    if (t == 0) {
        float recon = res[0] / (float)BQ;
        float kl = res[1] / (float)BQ + res[2] / (float)BQ;
        out[0] = -recon - 0.001f * kl;
        out[1] = recon;
        out[2] = kl;
    }
}

extern "C" void kernel_launch(void* const* d_in, const int* in_sizes, int n_in,
                              void* d_out, int out_size)
{
    const float* x      = (const float*)d_in[0];
    const float* rho    = (const float*)d_in[1];
    const float* z_init = (const float*)d_in[2];
    const float* grnd   = (const float*)d_in[3];
    const float* eW1    = (const float*)d_in[4];
    const float* eb1    = (const float*)d_in[5];
    const float* eg1    = (const float*)d_in[6];
    const float* ebe1   = (const float*)d_in[7];
    const float* eW2    = (const float*)d_in[8];
    const float* eb2    = (const float*)d_in[9];
    const float* dW1    = (const float*)d_in[10];
    const float* db1    = (const float*)d_in[11];
    const float* dg1    = (const float*)d_in[12];
    const float* dbe1   = (const float*)d_in[13];
    const float* dW2    = (const float*)d_in[14];
    const float* db2    = (const float*)d_in[15];
    const float* rbm_h  = (const float*)d_in[16];
    const float* rbm_W  = (const float*)d_in[17];

    float* out = (float*)d_out;
    float* out_z = out + 3;
    float* out_zeta = out + 3 + (size_t)BQ * LD;

    float *p_h, *p_q, *p_zeta, *p_zb, *p_rp, *p_rn, *p_part;
    __nv_bfloat16 *p_hb, *p_w2b;
    cudaGetSymbolAddress((void**)&p_h, g_h);
    cudaGetSymbolAddress((void**)&p_hb, g_hb);
    cudaGetSymbolAddress((void**)&p_w2b, g_w2b);
    cudaGetSymbolAddress((void**)&p_q, g_q);
    cudaGetSymbolAddress((void**)&p_zeta, g_zeta);
    cudaGetSymbolAddress((void**)&p_zb, g_zb);
    cudaGetSymbolAddress((void**)&p_rp, g_rowpos);
    cudaGetSymbolAddress((void**)&p_rn, g_rowneg);
    cudaGetSymbolAddress((void**)&p_part, g_part);

    static int smem_set = 0;
    int gibbs_smem = (256 * WP + 2 * GR * ZP) * 2 + 256 * 4;
    if (!smem_set) {
        cudaFuncSetAttribute(gibbs_fused, cudaFuncAttributeMaxDynamicSharedMemorySize, gibbs_smem);
        smem_set = 1;
    }

    cvt_w2<<<(HD * DIN + 255) / 256, 256>>>(dW2);

    // encoder layer 1 (tf32x3 tensor, fp32-equivalent)
    gemm_tf32<<<dim3(4, 128), 256>>>(x, DIN, eW1, HD, eb1, p_h, HD, DIN);
    bn_stats_part<<<dim3(16, 16), dim3(32, 8)>>>(p_h);
    bn_final<<<2, 256>>>(eg1, ebe1);
    bn_relu<0><<<8192, 256>>>();
    // encoder layer 2 + reparam (fp32 f32x2)
    gemm_k<1><<<dim3(2, 128), 256>>>(p_h, HD, eW2, LD, eb2, p_q, LD,
                                     BQ, LD, HD, rho, p_zeta, out_z, out_zeta);
    // decoder layer 1 (tf32x3 tensor)
    gemm_tf32<<<dim3(4, 128), 256>>>(p_zeta, LD, dW1, HD, db1, p_h, HD, LD);
    bn_stats_part<<<dim3(16, 16), dim3(32, 8)>>>(p_h);
    bn_final<<<2, 256>>>(dg1, dbe1);
    bn_relu<1><<<8192, 256>>>();
    // decoder layer 2 + fused recon loss (bf16 tensor)
    gemm4_loss<<<dim3(32, 128), 256>>>(p_hb, p_w2b, db2, x, p_part);
    // fused 30-step Gibbs (bf16 tensor)
    gibbs_fused<<<BQ / GR, 256, gibbs_smem>>>(z_init, grnd, rbm_h, rbm_W, p_zb);
    // kl terms
    kl_rows<<<1024, 256>>>(out_z, p_q, rbm_h, rbm_W, p_rp, 1);
    kl_rows<<<1024, 256>>>(p_zb, nullptr, rbm_h, rbm_W, p_rn, 0);
    finalize_k<<<1, 256>>>(out);
}